// round 8
// baseline (speedup 1.0000x reference)
#include <cuda_runtime.h>
#include <cuda_bf16.h>
#include <math.h>
#include <stdint.h>

// ---------------- problem dims ----------------
#define D      512
#define H      8
#define DH     64
#define DFF    2048
#define DLAT   128
#define NTOK   1024
#define NCODES 2048
#define NGROUPS 64
#define T_ENC  128
#define BT     8
#define NSEQ   16
#define BENC   (BT*NSEQ)      // 128
#define T_DEC  1024
#define M_ENC  (T_ENC*BENC)   // 16384
#define M_DEC  (T_DEC*BT)     // 8192

// ---------------- scratch layout (floats) ----------------
static const size_t OFF_ACT  = 0;                       // 16384*512
static const size_t OFF_TMP  = OFF_ACT  + (size_t)M_ENC*D;
static const size_t OFF_QKV  = OFF_TMP  + (size_t)M_ENC*D;      // 16384*1536
static const size_t OFF_ATT  = OFF_QKV  + (size_t)M_ENC*3*D;
static const size_t OFF_FFN  = OFF_ATT  + (size_t)M_ENC*D;      // 16384*2048
static const size_t OFF_SEGP = OFF_FFN  + (size_t)M_ENC*DFF;    // 8192*512
static const size_t OFF_DSEG = OFF_SEGP + (size_t)M_DEC*D;      // 8192*128
static const size_t OFF_LOG  = OFF_DSEG + (size_t)M_DEC*DLAT;   // 8192*1024
static const size_t OFF_DIFF = OFF_LOG  + (size_t)M_DEC*NTOK;
static const size_t SCRATCH_FLOATS = OFF_DIFF + 16;

__device__ __align__(16) float g_scratch[SCRATCH_FLOATS];

// ---------------- SGEMM: C[M,N] = A[M,K] @ B[K,N] (+bias)(+relu) ----------------
// BM=BN=128, BK=8, 256 threads, 8x8 per thread. M%128==0, N%128==0, K%8==0.
__global__ __launch_bounds__(256, 2) void sgemm_kernel(
    const float* __restrict__ A, const float* __restrict__ B,
    const float* __restrict__ bias, float* __restrict__ C,
    int M, int N, int K, int relu)
{
    __shared__ float As[8][132];
    __shared__ float Bs[8][128];
    const int tid  = threadIdx.x;
    const int bm   = blockIdx.y << 7;
    const int bn   = blockIdx.x << 7;
    const int arow = tid >> 1;
    const int acol = (tid & 1) << 2;
    const int brow = tid >> 5;
    const int bcol = (tid & 31) << 2;
    const int tx   = tid & 15;
    const int ty   = tid >> 4;

    const float* Ag = A + (size_t)(bm + arow) * K + acol;
    const float* Bg = B + (size_t)brow * N + bn + bcol;

    float acc[8][8];
    #pragma unroll
    for (int i = 0; i < 8; i++)
        #pragma unroll
        for (int j = 0; j < 8; j++) acc[i][j] = 0.f;

    float4 av = *(const float4*)Ag;
    float4 bv = *(const float4*)Bg;

    for (int k0 = 0; k0 < K; k0 += 8) {
        As[acol + 0][arow] = av.x;
        As[acol + 1][arow] = av.y;
        As[acol + 2][arow] = av.z;
        As[acol + 3][arow] = av.w;
        *(float4*)&Bs[brow][bcol] = bv;
        __syncthreads();
        if (k0 + 8 < K) {
            av = *(const float4*)(Ag + k0 + 8);
            bv = *(const float4*)(Bg + (size_t)(k0 + 8) * N);
        }
        #pragma unroll
        for (int k = 0; k < 8; k++) {
            float4 a0 = *(const float4*)&As[k][ty * 8];
            float4 a1 = *(const float4*)&As[k][ty * 8 + 4];
            float4 b0 = *(const float4*)&Bs[k][tx * 8];
            float4 b1 = *(const float4*)&Bs[k][tx * 8 + 4];
            float ar[8] = {a0.x, a0.y, a0.z, a0.w, a1.x, a1.y, a1.z, a1.w};
            float br[8] = {b0.x, b0.y, b0.z, b0.w, b1.x, b1.y, b1.z, b1.w};
            #pragma unroll
            for (int i = 0; i < 8; i++)
                #pragma unroll
                for (int j = 0; j < 8; j++)
                    acc[i][j] = fmaf(ar[i], br[j], acc[i][j]);
        }
        __syncthreads();
    }
    #pragma unroll
    for (int i = 0; i < 8; i++) {
        float* Cp = C + (size_t)(bm + ty * 8 + i) * N + bn + tx * 8;
        #pragma unroll
        for (int jj = 0; jj < 2; jj++) {
            float4 v;
            v.x = acc[i][jj * 4 + 0]; v.y = acc[i][jj * 4 + 1];
            v.z = acc[i][jj * 4 + 2]; v.w = acc[i][jj * 4 + 3];
            if (bias) {
                const float* bp = bias + bn + tx * 8 + jj * 4;
                v.x += bp[0]; v.y += bp[1]; v.z += bp[2]; v.w += bp[3];
            }
            if (relu) {
                v.x = fmaxf(v.x, 0.f); v.y = fmaxf(v.y, 0.f);
                v.z = fmaxf(v.z, 0.f); v.w = fmaxf(v.w, 0.f);
            }
            *(float4*)(Cp + jj * 4) = v;
        }
    }
}

static inline void sgemm(const float* A, const float* B, const float* bias,
                         float* C, int M, int N, int K, int relu)
{
    dim3 grid(N >> 7, M >> 7);
    sgemm_kernel<<<grid, 256>>>(A, B, bias, C, M, N, K, relu);
}

// ---------------- fused attention (flash-style) ----------------
// qkv [T, Brow, 3D]; out [T, Brow, D]. 64 q-rows per block, dh=64.
__global__ __launch_bounds__(64) void attn_kernel(
    const float* __restrict__ qkv, float* __restrict__ out,
    int T, int Brow, int causal)
{
    __shared__ float Ks[64][68];
    __shared__ float Vs[64][68];
    const int tid = threadIdx.x;
    const int b = blockIdx.y >> 3;
    const int h = blockIdx.y & 7;
    const int t = blockIdx.x * 64 + tid;
    const int row3 = Brow * (3 * D);

    const float* qb = qkv + (size_t)t * row3 + b * (3 * D) + h * DH;
    float q[64];
    #pragma unroll
    for (int i = 0; i < 16; i++) {
        float4 v = *(const float4*)(qb + i * 4);
        q[4 * i + 0] = v.x; q[4 * i + 1] = v.y; q[4 * i + 2] = v.z; q[4 * i + 3] = v.w;
    }
    float o[64];
    #pragma unroll
    for (int i = 0; i < 64; i++) o[i] = 0.f;
    float m = -1e30f, l = 0.f;

    const int send = causal ? (blockIdx.x * 64 + 64) : T;
    for (int s0 = 0; s0 < send; s0 += 64) {
        #pragma unroll
        for (int i = 0; i < 16; i++) {
            int idx = i * 64 + tid;
            int s = idx >> 4;
            int c = (idx & 15) << 2;
            const float* kg = qkv + (size_t)(s0 + s) * row3 + b * (3 * D) + D + h * DH + c;
            *(float4*)&Ks[s][c] = *(const float4*)kg;
            *(float4*)&Vs[s][c] = *(const float4*)(kg + D);
        }
        __syncthreads();
        int smax = 64;
        if (causal) {
            int r = t - s0 + 1;
            smax = r < 64 ? (r < 0 ? 0 : r) : 64;
        }
        for (int s = 0; s < smax; s++) {
            float sc = 0.f;
            #pragma unroll
            for (int i = 0; i < 16; i++) {
                float4 kv = *(const float4*)&Ks[s][i * 4];
                sc = fmaf(q[4 * i + 0], kv.x, sc);
                sc = fmaf(q[4 * i + 1], kv.y, sc);
                sc = fmaf(q[4 * i + 2], kv.z, sc);
                sc = fmaf(q[4 * i + 3], kv.w, sc);
            }
            sc *= 0.125f;  // 1/sqrt(64)
            if (sc <= m) {
                float e = __expf(sc - m);
                l += e;
                #pragma unroll
                for (int i = 0; i < 16; i++) {
                    float4 vv = *(const float4*)&Vs[s][i * 4];
                    o[4 * i + 0] = fmaf(e, vv.x, o[4 * i + 0]);
                    o[4 * i + 1] = fmaf(e, vv.y, o[4 * i + 1]);
                    o[4 * i + 2] = fmaf(e, vv.z, o[4 * i + 2]);
                    o[4 * i + 3] = fmaf(e, vv.w, o[4 * i + 3]);
                }
            } else {
                float cc = __expf(m - sc);
                m = sc;
                l = fmaf(l, cc, 1.f);
                #pragma unroll
                for (int i = 0; i < 16; i++) {
                    float4 vv = *(const float4*)&Vs[s][i * 4];
                    o[4 * i + 0] = fmaf(o[4 * i + 0], cc, vv.x);
                    o[4 * i + 1] = fmaf(o[4 * i + 1], cc, vv.y);
                    o[4 * i + 2] = fmaf(o[4 * i + 2], cc, vv.z);
                    o[4 * i + 3] = fmaf(o[4 * i + 3], cc, vv.w);
                }
            }
        }
        __syncthreads();
    }
    float inv = 1.f / l;
    float* ob = out + (size_t)t * (Brow * D) + b * D + h * DH;
    #pragma unroll
    for (int i = 0; i < 16; i++) {
        float4 v;
        v.x = o[4 * i + 0] * inv; v.y = o[4 * i + 1] * inv;
        v.z = o[4 * i + 2] * inv; v.w = o[4 * i + 3] * inv;
        *(float4*)(ob + i * 4) = v;
    }
}

// ---------------- LayerNorm(x + r) * g + b, row length 512 ----------------
__global__ __launch_bounds__(128) void ln_kernel(
    const float* __restrict__ x, const float* __restrict__ r,
    const float* __restrict__ gam, const float* __restrict__ bet,
    float* __restrict__ out)
{
    __shared__ float red[4];
    const int row = blockIdx.x, tid = threadIdx.x;
    const float4 a  = ((const float4*)(x + (size_t)row * D))[tid];
    const float4 rr = ((const float4*)(r + (size_t)row * D))[tid];
    float v[4] = {a.x + rr.x, a.y + rr.y, a.z + rr.z, a.w + rr.w};
    float s = v[0] + v[1] + v[2] + v[3];
    #pragma unroll
    for (int o2 = 16; o2; o2 >>= 1) s += __shfl_xor_sync(0xffffffffu, s, o2);
    if ((tid & 31) == 0) red[tid >> 5] = s;
    __syncthreads();
    const float mean = (red[0] + red[1] + red[2] + red[3]) * (1.f / D);
    float d[4]; float ss = 0.f;
    #pragma unroll
    for (int j = 0; j < 4; j++) { d[j] = v[j] - mean; ss += d[j] * d[j]; }
    #pragma unroll
    for (int o2 = 16; o2; o2 >>= 1) ss += __shfl_xor_sync(0xffffffffu, ss, o2);
    __syncthreads();
    if ((tid & 31) == 0) red[tid >> 5] = ss;
    __syncthreads();
    const float var = (red[0] + red[1] + red[2] + red[3]) * (1.f / D);
    const float rstd = rsqrtf(var + 1e-5f);
    const float4 gg = ((const float4*)gam)[tid];
    const float4 bb = ((const float4*)bet)[tid];
    float4 o4;
    o4.x = d[0] * rstd * gg.x + bb.x;
    o4.y = d[1] * rstd * gg.y + bb.y;
    o4.z = d[2] * rstd * gg.z + bb.z;
    o4.w = d[3] * rstd * gg.w + bb.w;
    ((float4*)(out + (size_t)row * D))[tid] = o4;
}

// ---------------- embedding + sinusoid PE ----------------
__global__ __launch_bounds__(128) void embed_kernel(
    const int* __restrict__ inp, const float* __restrict__ emb,
    float* __restrict__ out, int Brow)
{
    const int bx = blockIdx.x;           // flattened (t, n) row
    const int t = bx / Brow;
    const int tok = inp[bx];
    const int tid = threadIdx.x;
    const float SCALE = 22.62741699796952f;  // sqrt(512)
    const float NEGC = -0.017988946039015984f;  // -ln(10000)/512
    float4 e = ((const float4*)(emb + (size_t)tok * D))[tid];
    float pe[4];
    const int d0 = tid * 4;
    #pragma unroll
    for (int j = 0; j < 4; j++) {
        int dd = d0 + j;
        int i2 = dd & ~1;
        float div = expf((float)i2 * NEGC);
        float ang = (float)t * div;
        pe[j] = (dd & 1) ? cosf(ang) : sinf(ang);
    }
    float4 o;
    o.x = e.x * SCALE + pe[0];
    o.y = e.y * SCALE + pe[1];
    o.z = e.z * SCALE + pe[2];
    o.w = e.w * SCALE + pe[3];
    ((float4*)(out + (size_t)bx * D))[tid] = o;
}

// ---------------- grouped VQ ----------------
__global__ __launch_bounds__(256) void vq_kernel(
    const float* __restrict__ mu, const float* __restrict__ cb,
    float* __restrict__ z_out, float* __restrict__ diffsum)
{
    __shared__ float cbs[NCODES * 2];
    __shared__ float red[8];
    for (int i = threadIdx.x; i < NCODES * 2; i += 256) cbs[i] = cb[i];
    __syncthreads();
    const int p = blockIdx.x * 256 + threadIdx.x;   // pair id 0..8191
    const float gx = mu[2 * p], gy = mu[2 * p + 1];
    const float gn = gx * gx + gy * gy;
    float best = 3.4e38f; int bi = 0;
    for (int c = 0; c < NCODES; c++) {
        float cx = cbs[2 * c], cy = cbs[2 * c + 1];
        float dd = (gn - 2.f * (gx * cx + gy * cy)) + (cx * cx + cy * cy);
        if (dd < best) { best = dd; bi = c; }
    }
    const float qx = cbs[2 * bi], qy = cbs[2 * bi + 1];
    z_out[2 * p]     = gx + (qx - gx);   // straight-through forward value
    z_out[2 * p + 1] = gy + (qy - gy);
    float dx = qx - gx, dy = qy - gy;
    float sq = dx * dx + dy * dy;
    #pragma unroll
    for (int o2 = 16; o2; o2 >>= 1) sq += __shfl_xor_sync(0xffffffffu, sq, o2);
    if ((threadIdx.x & 31) == 0) red[threadIdx.x >> 5] = sq;
    __syncthreads();
    if (threadIdx.x == 0) {
        float tot = 0.f;
        #pragma unroll
        for (int i = 0; i < 8; i++) tot += red[i];
        atomicAdd(diffsum, tot);
    }
}

__global__ void zero_kernel(float* p) { p[0] = 0.f; }
// diff = 2 * sum / (8192*2) = sum / 8192
__global__ void finalize_diff_kernel(const float* s, float* dst) { dst[0] = s[0] * (1.f / 8192.f); }

// ---------------- ragged segment gather: dec_seg_emb [T_DEC, BT, DLAT] ----------------
__global__ __launch_bounds__(32) void decseg_kernel(
    const int* __restrict__ seq_pos, const float* __restrict__ z,
    float* __restrict__ out)
{
    const int idx = blockIdx.x;       // t*BT + b
    const int t = idx >> 3;
    const int b = idx & 7;
    const int* p = seq_pos + b * (NSEQ + 1);
    int cnt = 0;
    #pragma unroll
    for (int i = 0; i < NSEQ + 1; i++) cnt += (p[i] <= t);
    const int seg = cnt - 1;
    float4 val = {0.f, 0.f, 0.f, 0.f};
    if (seg >= 0 && seg < NSEQ) {
        const float* zr = z + ((size_t)b * NSEQ + seg) * DLAT;
        val = ((const float4*)zr)[threadIdx.x];
    }
    ((float4*)(out + (size_t)idx * DLAT))[threadIdx.x] = val;
}

// ---------------- misc elementwise ----------------
__global__ void add_kernel(float* __restrict__ a, const float* __restrict__ b, int n4)
{
    int i = blockIdx.x * blockDim.x + threadIdx.x;
    if (i < n4) {
        float4 x = ((const float4*)a)[i];
        float4 y = ((const float4*)b)[i];
        x.x += y.x; x.y += y.y; x.z += y.z; x.w += y.w;
        ((float4*)a)[i] = x;
    }
}

__global__ void copy_kernel(const float* __restrict__ src, float* __restrict__ dst, int n)
{
    int i = blockIdx.x * blockDim.x + threadIdx.x;
    if (i < n) dst[i] = src[i];
}

// ---------------- orchestration ----------------
extern "C" void kernel_launch(void* const* d_in, const int* in_sizes, int n_in,
                              void* d_out, int out_size)
{
    const int*   enc_inp = (const int*)d_in[0];
    const int*   dec_inp = (const int*)d_in[1];
    const int*   seq_pos = (const int*)d_in[2];
    const float* emb     = (const float*)d_in[3];
    const float* eWqkv = (const float*)d_in[4];
    const float* eWo   = (const float*)d_in[5];
    const float* eln1g = (const float*)d_in[6];
    const float* eln1b = (const float*)d_in[7];
    const float* eln2g = (const float*)d_in[8];
    const float* eln2b = (const float*)d_in[9];
    const float* eW1   = (const float*)d_in[10];
    const float* eb1   = (const float*)d_in[11];
    const float* eW2   = (const float*)d_in[12];
    const float* eb2   = (const float*)d_in[13];
    const float* dWqkv = (const float*)d_in[14];
    const float* dWo   = (const float*)d_in[15];
    const float* dln1g = (const float*)d_in[16];
    const float* dln1b = (const float*)d_in[17];
    const float* dln2g = (const float*)d_in[18];
    const float* dln2b = (const float*)d_in[19];
    const float* dW1   = (const float*)d_in[20];
    const float* db1   = (const float*)d_in[21];
    const float* dW2   = (const float*)d_in[22];
    const float* db2   = (const float*)d_in[23];
    const float* W_mu  = (const float*)d_in[24];
    const float* b_mu  = (const float*)d_in[25];
    const float* cbk   = (const float*)d_in[26];
    const float* seg_W = (const float*)d_in[27];
    const float* seg_b = (const float*)d_in[28];
    const float* W_out = (const float*)d_in[29];
    const float* b_out = (const float*)d_in[30];

    float* S = nullptr;
    cudaGetSymbolAddress((void**)&S, g_scratch);
    float* ACT    = S + OFF_ACT;
    float* TMP    = S + OFF_TMP;
    float* QKV    = S + OFF_QKV;
    float* ATT    = S + OFF_ATT;
    float* FFN    = S + OFF_FFN;
    float* SEGP   = S + OFF_SEGP;
    float* DSEG   = S + OFF_DSEG;
    float* LOGITS = S + OFF_LOG;
    float* DIFFS  = S + OFF_DIFF;

    float* out        = (float*)d_out;
    float* out_mu     = out;                       // 16384
    float* out_z      = out + 16384;               // 16384
    float* out_diff   = out + 32768;               // 1
    float* out_logits = out + 32769;               // 8388608 (unaligned -> copy)

    // ===== encoder =====
    embed_kernel<<<M_ENC, 128>>>(enc_inp, emb, ACT, BENC);
    for (int i = 0; i < 4; i++) {
        sgemm(ACT, eWqkv + (size_t)i * D * 3 * D, nullptr, QKV, M_ENC, 3 * D, D, 0);
        attn_kernel<<<dim3(T_ENC / 64, BENC * H), 64>>>(QKV, ATT, T_ENC, BENC, 0);
        sgemm(ATT, eWo + (size_t)i * D * D, nullptr, TMP, M_ENC, D, D, 0);
        ln_kernel<<<M_ENC, 128>>>(ACT, TMP, eln1g + i * D, eln1b + i * D, ACT);
        sgemm(ACT, eW1 + (size_t)i * D * DFF, eb1 + (size_t)i * DFF, FFN, M_ENC, DFF, D, 1);
        sgemm(FFN, eW2 + (size_t)i * DFF * D, eb2 + (size_t)i * D, TMP, M_ENC, D, DFF, 0);
        ln_kernel<<<M_ENC, 128>>>(ACT, TMP, eln2g + i * D, eln2b + i * D, ACT);
    }

    // ===== mu + VQ =====
    sgemm(ACT, W_mu, b_mu, out_mu, BENC, DLAT, D, 0);   // x[0] = first 128 rows
    zero_kernel<<<1, 1>>>(DIFFS);
    vq_kernel<<<(BENC * NGROUPS) / 256, 256>>>(out_mu, cbk, out_z, DIFFS);
    finalize_diff_kernel<<<1, 1>>>(DIFFS, out_diff);

    // ===== segment conditioning =====
    decseg_kernel<<<M_DEC, 32>>>(seq_pos, out_z, DSEG);
    sgemm(DSEG, seg_W, seg_b, SEGP, M_DEC, D, DLAT, 0);

    // ===== decoder =====
    embed_kernel<<<M_DEC, 128>>>(dec_inp, emb, ACT, BT);
    for (int i = 0; i < 6; i++) {
        add_kernel<<<(M_DEC * D / 4 + 255) / 256, 256>>>(ACT, SEGP, M_DEC * D / 4);
        sgemm(ACT, dWqkv + (size_t)i * D * 3 * D, nullptr, QKV, M_DEC, 3 * D, D, 0);
        attn_kernel<<<dim3(T_DEC / 64, BT * H), 64>>>(QKV, ATT, T_DEC, BT, 1);
        sgemm(ATT, dWo + (size_t)i * D * D, nullptr, TMP, M_DEC, D, D, 0);
        ln_kernel<<<M_DEC, 128>>>(ACT, TMP, dln1g + i * D, dln1b + i * D, ACT);
        sgemm(ACT, dW1 + (size_t)i * D * DFF, db1 + (size_t)i * DFF, FFN, M_DEC, DFF, D, 1);
        sgemm(FFN, dW2 + (size_t)i * DFF * D, db2 + (size_t)i * D, TMP, M_DEC, D, DFF, 0);
        ln_kernel<<<M_DEC, 128>>>(ACT, TMP, dln2g + i * D, dln2b + i * D, ACT);
    }

    // ===== logits =====
    sgemm(ACT, W_out, b_out, LOGITS, M_DEC, NTOK, D, 0);
    copy_kernel<<<(M_DEC * NTOK + 255) / 256, 256>>>(LOGITS, out_logits, M_DEC * NTOK);
}